// round 1
// baseline (speedup 1.0000x reference)
#include <cuda_runtime.h>
#include <math.h>

// Problem constants (fixed by the reference: N=100000, D=64)
#define NN 100000
#define DD 64
#define EPSN 1e-15f
#define ATANH_CLIP (1.0f - 1e-7f)

// Scratch (allocation-free: __device__ globals)
__device__ float g_h[NN * DD];      // post-linear tangent features
__device__ float g_neigh[NN * DD];  // scatter accumulator
__device__ float g_x[NN * DD];      // intermediate layer output
__device__ int   g_deg[NN];         // in-degree

// ---------------------------------------------------------------------------
// zeroing kernels
// ---------------------------------------------------------------------------
__global__ void k_zero_deg() {
    int i = blockIdx.x * blockDim.x + threadIdx.x;
    if (i < NN) g_deg[i] = 0;
}

__global__ void k_zero_neigh() {
    int i = blockIdx.x * blockDim.x + threadIdx.x;
    int total = NN * DD / 4;
    if (i < total) reinterpret_cast<float4*>(g_neigh)[i] = make_float4(0.f, 0.f, 0.f, 0.f);
}

// ---------------------------------------------------------------------------
// degree histogram
// ---------------------------------------------------------------------------
__global__ void k_deg(const int* __restrict__ dst, int E) {
    int e = blockIdx.x * blockDim.x + threadIdx.x;
    if (e < E) atomicAdd(&g_deg[__ldg(&dst[e])], 1);
}

// ---------------------------------------------------------------------------
// fused logmap0 + linear:  h = (artanh(sc*||x||)/(sc*||x||) * x) @ W^T + b
// one warp per node; W transposed into padded shared memory
// blockDim = 256 (8 warps)
// ---------------------------------------------------------------------------
__global__ void k_logmap_linear(const float* __restrict__ x_in,
                                const float* __restrict__ W,
                                const float* __restrict__ b,
                                const float* __restrict__ curv) {
    __shared__ float Ws[DD][DD + 1];  // Ws[k][j] = W[j][k]
    __shared__ float ts[8][DD];       // per-warp tangent row

    int tid = threadIdx.x;
    // cooperative transpose load of W (4096 elems / 256 threads = 16 each)
    for (int i = tid; i < DD * DD; i += 256) {
        int j = i >> 6;
        int k = i & 63;
        Ws[k][j] = W[i];
    }
    __syncthreads();

    float c = fabsf(__ldg(&curv[0]));
    float sc = sqrtf(c);

    int warp = tid >> 5;
    int lane = tid & 31;
    int node = blockIdx.x * 8 + warp;
    if (node >= NN) return;

    // load row (2 floats per lane), compute squared norm
    const float2 xv = reinterpret_cast<const float2*>(x_in + (size_t)node * DD)[lane];
    float ss = xv.x * xv.x + xv.y * xv.y;
    #pragma unroll
    for (int off = 16; off > 0; off >>= 1)
        ss += __shfl_xor_sync(0xffffffffu, ss, off);

    float norm = fmaxf(sqrtf(ss), EPSN);
    float arg = fminf(sc * norm, ATANH_CLIP);
    float factor = atanhf(arg) / (sc * norm);

    ts[warp][2 * lane]     = xv.x * factor;
    ts[warp][2 * lane + 1] = xv.y * factor;
    __syncwarp();

    // each lane computes outputs j = lane and j = lane + 32
    int j1 = lane, j2 = lane + 32;
    float acc1 = __ldg(&b[j1]);
    float acc2 = __ldg(&b[j2]);
    #pragma unroll
    for (int k = 0; k < DD; k++) {
        float tk = ts[warp][k];
        acc1 = fmaf(tk, Ws[k][j1], acc1);
        acc2 = fmaf(tk, Ws[k][j2], acc2);
    }
    float* hrow = g_h + (size_t)node * DD;
    hrow[j1] = acc1;
    hrow[j2] = acc2;
}

// ---------------------------------------------------------------------------
// scatter: neigh[dst[e]] += h[src[e]]   (vectorized red.global.add.v4.f32)
// thread handles one (edge, 16B chunk) pair; D/4 = 16 chunks per edge
// ---------------------------------------------------------------------------
__global__ void k_scatter(const int* __restrict__ src,
                          const int* __restrict__ dst, int E) {
    int idx = blockIdx.x * blockDim.x + threadIdx.x;
    if (idx >= E * (DD / 4)) return;
    int e = idx >> 4;        // edge
    int cchunk = idx & 15;   // float4 chunk within the row

    int s = __ldg(&src[e]);
    int d = __ldg(&dst[e]);

    const float4 v = reinterpret_cast<const float4*>(g_h)[(size_t)s * (DD / 4) + cchunk];
    float4* outp = reinterpret_cast<float4*>(g_neigh) + (size_t)d * (DD / 4) + cchunk;
    asm volatile("red.global.add.v4.f32 [%0], {%1, %2, %3, %4};"
                 :: "l"(outp), "f"(v.x), "f"(v.y), "f"(v.z), "f"(v.w)
                 : "memory");
}

// ---------------------------------------------------------------------------
// fused inv-degree mean + expmap0:
//   u = neigh * inv_deg;  out = tanh(sc*||u||)/(sc*||u||) * u
// one warp per node, blockDim = 256
// ---------------------------------------------------------------------------
__global__ void k_mean_expmap(float* __restrict__ x_out,
                              const float* __restrict__ curv) {
    int tid = threadIdx.x;
    int warp = tid >> 5;
    int lane = tid & 31;
    int node = blockIdx.x * 8 + warp;
    if (node >= NN) return;

    float c = fabsf(__ldg(&curv[0]));
    float sc = sqrtf(c);

    int deg = g_deg[node];
    float inv_deg = (deg > 0) ? (1.0f / (float)deg) : 0.0f;

    float2 uv = reinterpret_cast<const float2*>(g_neigh + (size_t)node * DD)[lane];
    uv.x *= inv_deg;
    uv.y *= inv_deg;

    float ss = uv.x * uv.x + uv.y * uv.y;
    #pragma unroll
    for (int off = 16; off > 0; off >>= 1)
        ss += __shfl_xor_sync(0xffffffffu, ss, off);

    float norm = fmaxf(sqrtf(ss), EPSN);
    float factor = tanhf(sc * norm) / (sc * norm);

    float2 ov = make_float2(uv.x * factor, uv.y * factor);
    reinterpret_cast<float2*>(x_out + (size_t)node * DD)[lane] = ov;
}

// ---------------------------------------------------------------------------
// launch
// ---------------------------------------------------------------------------
extern "C" void kernel_launch(void* const* d_in, const int* in_sizes, int n_in,
                              void* d_out, int out_size) {
    const int*   src  = (const int*)d_in[0];
    const int*   dst  = (const int*)d_in[1];
    const float* emb  = (const float*)d_in[2];
    const float* W1   = (const float*)d_in[3];
    const float* b1   = (const float*)d_in[4];
    const float* W2   = (const float*)d_in[5];
    const float* b2   = (const float*)d_in[6];
    const float* curv = (const float*)d_in[7];
    const int E = in_sizes[0];

    float* out = (float*)d_out;

    const int node_blocks = (NN + 7) / 8;             // warp per node, 8 warps/block
    const int zero_blocks = (NN * DD / 4 + 255) / 256;
    const int scat_blocks = (E * (DD / 4) + 255) / 256;

    // degree (once per launch)
    k_zero_deg<<<(NN + 255) / 256, 256>>>();
    k_deg<<<(E + 255) / 256, 256>>>(dst, E);

    // layer 1: emb -> g_x
    k_zero_neigh<<<zero_blocks, 256>>>();
    k_logmap_linear<<<node_blocks, 256>>>(emb, W1, b1, curv);
    k_scatter<<<scat_blocks, 256>>>(src, dst, E);
    k_mean_expmap<<<node_blocks, 256>>>(g_x, curv);

    // layer 2: g_x -> out
    k_zero_neigh<<<zero_blocks, 256>>>();
    k_logmap_linear<<<node_blocks, 256>>>(g_x, W2, b2, curv);
    k_scatter<<<scat_blocks, 256>>>(src, dst, E);
    k_mean_expmap<<<node_blocks, 256>>>(out, curv);
}

// round 3
// speedup vs baseline: 1.2533x; 1.2533x over previous
#include <cuda_runtime.h>
#include <math.h>

#define NN 100000
#define DD 64
#define EPSN 1e-15f
#define ATANH_CLIP (1.0f - 1e-7f)
#define EMAX 1300000
#define SCANB 1024
#define NB ((NN + SCANB - 1) / SCANB)   // 98

// ---------------------------------------------------------------- scratch
__device__ float g_h[NN * DD];    // post-linear tangent features
__device__ float g_x[NN * DD];    // intermediate layer output
__device__ int   g_deg[NN];
__device__ int   g_start[NN + 1]; // CSR row offsets
__device__ int   g_incl[NN];      // local inclusive scan
__device__ int   g_bsum[NB];
__device__ int   g_boff[NB];
__device__ int   g_cursor[NN];
__device__ int   g_csr[EMAX];     // src ids grouped by dst

// ---------------------------------------------------------------- degree
__global__ void k_zero_deg() {
    int i = blockIdx.x * blockDim.x + threadIdx.x;
    if (i < NN) g_deg[i] = 0;
}

__global__ void k_deg(const int* __restrict__ dst, int E) {
    int e = blockIdx.x * blockDim.x + threadIdx.x;
    if (e < E) atomicAdd(&g_deg[__ldg(&dst[e])], 1);
}

// ---------------------------------------------------------------- scan (3-pass)
__global__ void k_scan_local() {
    __shared__ int ws[32];
    int tid = threadIdx.x;
    int i = blockIdx.x * SCANB + tid;
    int lane = tid & 31, wid = tid >> 5;

    int v = (i < NN) ? g_deg[i] : 0;
    int x = v;
    #pragma unroll
    for (int o = 1; o < 32; o <<= 1) {
        int y = __shfl_up_sync(0xffffffffu, x, o);
        if (lane >= o) x += y;
    }
    if (lane == 31) ws[wid] = x;
    __syncthreads();
    if (wid == 0) {
        int s = ws[lane];
        #pragma unroll
        for (int o = 1; o < 32; o <<= 1) {
            int y = __shfl_up_sync(0xffffffffu, s, o);
            if (lane >= o) s += y;
        }
        ws[lane] = s;
    }
    __syncthreads();
    int incl = x + (wid > 0 ? ws[wid - 1] : 0);
    if (i < NN) g_incl[i] = incl;
    if (tid == SCANB - 1) g_bsum[blockIdx.x] = incl;
}

__global__ void k_scan_spine() {  // 1 block, 128 threads
    __shared__ int ws[4];
    int tid = threadIdx.x;
    int lane = tid & 31, wid = tid >> 5;
    int v = (tid < NB) ? g_bsum[tid] : 0;
    int x = v;
    #pragma unroll
    for (int o = 1; o < 32; o <<= 1) {
        int y = __shfl_up_sync(0xffffffffu, x, o);
        if (lane >= o) x += y;
    }
    if (lane == 31) ws[wid] = x;
    __syncthreads();
    int off = 0;
    for (int w = 0; w < wid; w++) off += ws[w];
    if (tid < NB) g_boff[tid] = x - v + off;  // exclusive block offset
}

__global__ void k_scan_add() {
    int i = blockIdx.x * SCANB + threadIdx.x;
    if (i < NN) {
        g_start[i + 1] = g_incl[i] + g_boff[blockIdx.x];
        g_cursor[i] = 0;
    }
    if (i == 0) g_start[0] = 0;
}

__global__ void k_fill(const int* __restrict__ src,
                       const int* __restrict__ dst, int E) {
    int e = blockIdx.x * blockDim.x + threadIdx.x;
    if (e < E) {
        int d = __ldg(&dst[e]);
        int p = g_start[d] + atomicAdd(&g_cursor[d], 1);
        g_csr[p] = __ldg(&src[e]);
    }
}

// ---------------------------------------------------------------- fused logmap + GEMM
// TILE_M=128 nodes per block, 256 threads, 8 rows x 4 cols per thread.
// Dynamic SMEM: Xs[128][68] (scaled tangent), WsT[64][68] (W transposed)
#define XPAD 68
__global__ __launch_bounds__(256)
void k_linear(const float* __restrict__ x_in,
              const float* __restrict__ W,
              const float* __restrict__ b,
              const float* __restrict__ curv) {
    extern __shared__ float smem[];
    float* Xs  = smem;                    // 128*68
    float* WsT = smem + 128 * XPAD;       // 64*68 : WsT[k][j] = W[j][k]

    const int tid = threadIdx.x;
    const int rowbase = blockIdx.x * 128;

    // load W transposed: idx = j*64+k -> WsT[k*68+j]
    for (int idx = tid; idx < DD * DD; idx += 256) {
        int j = idx >> 6, k = idx & 63;
        WsT[k * XPAD + j] = W[idx];
    }

    // load X tile (raw) into Xs, zero-fill OOB rows
    const float4* in4 = reinterpret_cast<const float4*>(x_in);
    float4* Xs4 = reinterpret_cast<float4*>(Xs);
    for (int idx = tid; idx < 128 * 16; idx += 256) {
        int r = idx >> 4, c4 = idx & 15;
        int row = rowbase + r;
        float4 v = (row < NN) ? in4[(size_t)row * 16 + c4]
                              : make_float4(0.f, 0.f, 0.f, 0.f);
        Xs4[r * (XPAD / 4) + c4] = v;
    }
    __syncthreads();

    float c = fabsf(__ldg(&curv[0]));
    float sc = sqrtf(c);

    // per-row logmap factor, scale in place (threads 0..127)
    if (tid < 128) {
        float ss = 0.f;
        #pragma unroll
        for (int i = 0; i < 16; i++) {
            float4 v = Xs4[tid * (XPAD / 4) + i];
            ss += v.x * v.x + v.y * v.y + v.z * v.z + v.w * v.w;
        }
        float norm = fmaxf(sqrtf(ss), EPSN);
        float arg = fminf(sc * norm, ATANH_CLIP);
        float f = atanhf(arg) / (sc * norm);
        #pragma unroll
        for (int i = 0; i < 16; i++) {
            float4 v = Xs4[tid * (XPAD / 4) + i];
            v.x *= f; v.y *= f; v.z *= f; v.w *= f;
            Xs4[tid * (XPAD / 4) + i] = v;
        }
    }
    __syncthreads();

    // register-tiled GEMM: h = T @ W^T  (T[r][k] * W[j][k])
    const int tx = tid & 15;   // col group: cols tx*4 .. tx*4+3
    const int ty = tid >> 4;   // row group: rows ty*8 .. ty*8+7
    const float4* WsT4 = reinterpret_cast<const float4*>(WsT);

    float acc[8][4];
    #pragma unroll
    for (int i = 0; i < 8; i++)
        #pragma unroll
        for (int j = 0; j < 4; j++) acc[i][j] = 0.f;

    #pragma unroll
    for (int k4 = 0; k4 < 16; k4++) {
        float4 xr[8];
        #pragma unroll
        for (int i = 0; i < 8; i++)
            xr[i] = Xs4[(ty * 8 + i) * (XPAD / 4) + k4];
        float4 wr[4];
        #pragma unroll
        for (int kk = 0; kk < 4; kk++)
            wr[kk] = WsT4[(k4 * 4 + kk) * (XPAD / 4) + tx];
        #pragma unroll
        for (int kk = 0; kk < 4; kk++) {
            #pragma unroll
            for (int i = 0; i < 8; i++) {
                float xv = (kk == 0) ? xr[i].x : (kk == 1) ? xr[i].y
                         : (kk == 2) ? xr[i].z : xr[i].w;
                acc[i][0] = fmaf(xv, wr[kk].x, acc[i][0]);
                acc[i][1] = fmaf(xv, wr[kk].y, acc[i][1]);
                acc[i][2] = fmaf(xv, wr[kk].z, acc[i][2]);
                acc[i][3] = fmaf(xv, wr[kk].w, acc[i][3]);
            }
        }
    }

    float b0 = __ldg(&b[tx * 4 + 0]);
    float b1 = __ldg(&b[tx * 4 + 1]);
    float b2 = __ldg(&b[tx * 4 + 2]);
    float b3 = __ldg(&b[tx * 4 + 3]);

    float4* h4 = reinterpret_cast<float4*>(g_h);
    #pragma unroll
    for (int i = 0; i < 8; i++) {
        int row = rowbase + ty * 8 + i;
        if (row < NN)
            h4[(size_t)row * 16 + tx] =
                make_float4(acc[i][0] + b0, acc[i][1] + b1,
                            acc[i][2] + b2, acc[i][3] + b3);
    }
}

// ---------------------------------------------------------------- fused gather-mean-expmap
// warp per node: sum h[src] rows over CSR range, *1/deg, expmap0, write
__global__ __launch_bounds__(256)
void k_agg(float* __restrict__ x_out, const float* __restrict__ curv) {
    int tid = threadIdx.x;
    int warp = tid >> 5, lane = tid & 31;
    int node = blockIdx.x * 8 + warp;
    if (node >= NN) return;

    int rs = g_start[node];
    int re = g_start[node + 1];

    float ax = 0.f, ay = 0.f;
    const float2* h2 = reinterpret_cast<const float2*>(g_h);

    for (int eb = rs; eb < re; eb += 32) {
        int idx = eb + lane;
        int sid = (idx < re) ? g_csr[idx] : 0;
        int n = min(32, re - eb);
        for (int i = 0; i < n; i++) {
            int s = __shfl_sync(0xffffffffu, sid, i);
            float2 v = __ldg(&h2[(size_t)s * 32 + lane]);
            ax += v.x; ay += v.y;
        }
    }

    float inv_deg = (re > rs) ? (1.0f / (float)(re - rs)) : 0.0f;
    float ux = ax * inv_deg, uy = ay * inv_deg;

    float ss = ux * ux + uy * uy;
    #pragma unroll
    for (int off = 16; off > 0; off >>= 1)
        ss += __shfl_xor_sync(0xffffffffu, ss, off);

    float c = fabsf(__ldg(&curv[0]));
    float sc = sqrtf(c);
    float norm = fmaxf(sqrtf(ss), EPSN);
    float factor = tanhf(sc * norm) / (sc * norm);

    reinterpret_cast<float2*>(x_out)[(size_t)node * 32 + lane] =
        make_float2(ux * factor, uy * factor);
}

// ---------------------------------------------------------------- launch
extern "C" void kernel_launch(void* const* d_in, const int* in_sizes, int n_in,
                              void* d_out, int out_size) {
    const int*   src  = (const int*)d_in[0];
    const int*   dst  = (const int*)d_in[1];
    const float* emb  = (const float*)d_in[2];
    const float* W1   = (const float*)d_in[3];
    const float* b1   = (const float*)d_in[4];
    const float* W2   = (const float*)d_in[5];
    const float* b2   = (const float*)d_in[6];
    const float* curv = (const float*)d_in[7];
    const int E = in_sizes[0];
    float* out = (float*)d_out;

    const int smem_bytes = (128 * XPAD + 64 * XPAD) * sizeof(float);
    cudaFuncSetAttribute(k_linear, cudaFuncAttributeMaxDynamicSharedMemorySize,
                         smem_bytes);

    const int lin_blocks  = (NN + 127) / 128;
    const int node_blocks = (NN + 7) / 8;

    // CSR build (once per launch; reused by both layers)
    k_zero_deg<<<(NN + 255) / 256, 256>>>();
    k_deg<<<(E + 255) / 256, 256>>>(dst, E);
    k_scan_local<<<NB, SCANB>>>();
    k_scan_spine<<<1, 128>>>();
    k_scan_add<<<NB, SCANB>>>();
    k_fill<<<(E + 255) / 256, 256>>>(src, dst, E);

    // layer 1: emb -> g_x
    k_linear<<<lin_blocks, 256, smem_bytes>>>(emb, W1, b1, curv);
    k_agg<<<node_blocks, 256>>>(g_x, curv);

    // layer 2: g_x -> out
    k_linear<<<lin_blocks, 256, smem_bytes>>>(g_x, W2, b2, curv);
    k_agg<<<node_blocks, 256>>>(out, curv);
}

// round 5
// speedup vs baseline: 1.2712x; 1.0143x over previous
#include <cuda_runtime.h>
#include <math.h>

#define NN 100000
#define DD 64
#define EPSN 1e-15f
#define ATANH_CLIP (1.0f - 1e-7f)
#define EMAX 1300000
#define SCANB 1024
#define NB ((NN + SCANB - 1) / SCANB)   // 98

// ---------------------------------------------------------------- scratch
__device__ float g_h[NN * DD];    // post-linear tangent features
__device__ float g_x[NN * DD];    // layer-1 tangent mean (m1)
__device__ int   g_deg[NN];
__device__ int   g_incl[NN];      // local inclusive scan
__device__ int   g_bsum[NB];
__device__ int   g_start[NN + 1]; // CSR row offsets
__device__ int   g_cursor[NN];    // running absolute fill position
__device__ int   g_csr[EMAX];     // src ids grouped by dst

// ---------------------------------------------------------------- degree
__global__ void k_zero_deg() {
    int i = blockIdx.x * blockDim.x + threadIdx.x;
    if (i < NN) g_deg[i] = 0;
}

__global__ void k_deg(const int* __restrict__ dst, int E) {
    int e = blockIdx.x * blockDim.x + threadIdx.x;
    if (e < E) atomicAdd(&g_deg[__ldg(&dst[e])], 1);
}

// ---------------------------------------------------------------- scan
__global__ void k_scan_local() {
    __shared__ int ws[32];
    int tid = threadIdx.x;
    int i = blockIdx.x * SCANB + tid;
    int lane = tid & 31, wid = tid >> 5;

    int v = (i < NN) ? g_deg[i] : 0;
    int x = v;
    #pragma unroll
    for (int o = 1; o < 32; o <<= 1) {
        int y = __shfl_up_sync(0xffffffffu, x, o);
        if (lane >= o) x += y;
    }
    if (lane == 31) ws[wid] = x;
    __syncthreads();
    if (wid == 0) {
        int s = ws[lane];
        #pragma unroll
        for (int o = 1; o < 32; o <<= 1) {
            int y = __shfl_up_sync(0xffffffffu, s, o);
            if (lane >= o) s += y;
        }
        ws[lane] = s;
    }
    __syncthreads();
    int incl = x + (wid > 0 ? ws[wid - 1] : 0);
    if (i < NN) g_incl[i] = incl;
    if (tid == SCANB - 1) g_bsum[blockIdx.x] = incl;
}

// spine folded in: each block sums g_bsum[0..bid) itself (<= 97 ints)
__global__ void k_scan_add() {
    __shared__ int soff;
    int tid = threadIdx.x;
    if (tid < 32) {
        int s = 0;
        for (int j = tid; j < (int)blockIdx.x; j += 32) s += g_bsum[j];
        #pragma unroll
        for (int o = 16; o > 0; o >>= 1)
            s += __shfl_xor_sync(0xffffffffu, s, o);
        if (tid == 0) soff = s;
    }
    __syncthreads();
    int i = blockIdx.x * SCANB + tid;
    if (i < NN) {
        int incl = g_incl[i] + soff;      // inclusive prefix
        g_start[i + 1] = incl;
        g_cursor[i] = incl - g_deg[i];    // absolute row start
    }
    if (i == 0) g_start[0] = 0;
}

__global__ void k_fill(const int* __restrict__ src,
                       const int* __restrict__ dst, int E) {
    int e = blockIdx.x * blockDim.x + threadIdx.x;
    if (e < E) {
        int d = __ldg(&dst[e]);
        int p = atomicAdd(&g_cursor[d], 1);
        g_csr[p] = __ldg(&src[e]);
    }
}

// ---------------------------------------------------------------- fused (logmap?) + GEMM
// TILE_M=128 nodes/block, 256 threads, 8x4 outputs/thread.
#define XPAD 68
template <bool DO_LOG>
__global__ __launch_bounds__(256)
void k_linear(const float* __restrict__ x_in,
              const float* __restrict__ W,
              const float* __restrict__ b,
              const float* __restrict__ curv) {
    extern __shared__ float smem[];
    float* Xs  = smem;                    // 128*68
    float* WsT = smem + 128 * XPAD;       // 64*68 : WsT[k][j] = W[j][k]

    const int tid = threadIdx.x;
    const int rowbase = blockIdx.x * 128;

    for (int idx = tid; idx < DD * DD; idx += 256) {
        int j = idx >> 6, k = idx & 63;
        WsT[k * XPAD + j] = W[idx];
    }

    const float4* in4 = reinterpret_cast<const float4*>(x_in);
    float4* Xs4 = reinterpret_cast<float4*>(Xs);
    for (int idx = tid; idx < 128 * 16; idx += 256) {
        int r = idx >> 4, c4 = idx & 15;
        int row = rowbase + r;
        float4 v = (row < NN) ? in4[(size_t)row * 16 + c4]
                              : make_float4(0.f, 0.f, 0.f, 0.f);
        Xs4[r * (XPAD / 4) + c4] = v;
    }
    __syncthreads();

    if (DO_LOG) {
        float c = fabsf(__ldg(&curv[0]));
        float sc = sqrtf(c);
        if (tid < 128) {
            float ss = 0.f;
            #pragma unroll
            for (int i = 0; i < 16; i++) {
                float4 v = Xs4[tid * (XPAD / 4) + i];
                ss += v.x * v.x + v.y * v.y + v.z * v.z + v.w * v.w;
            }
            float norm = fmaxf(sqrtf(ss), EPSN);
            float arg = fminf(sc * norm, ATANH_CLIP);
            float f = atanhf(arg) / (sc * norm);
            #pragma unroll
            for (int i = 0; i < 16; i++) {
                float4 v = Xs4[tid * (XPAD / 4) + i];
                v.x *= f; v.y *= f; v.z *= f; v.w *= f;
                Xs4[tid * (XPAD / 4) + i] = v;
            }
        }
        __syncthreads();
    }

    const int tx = tid & 15;
    const int ty = tid >> 4;
    const float4* WsT4 = reinterpret_cast<const float4*>(WsT);

    float acc[8][4];
    #pragma unroll
    for (int i = 0; i < 8; i++)
        #pragma unroll
        for (int j = 0; j < 4; j++) acc[i][j] = 0.f;

    #pragma unroll
    for (int k4 = 0; k4 < 16; k4++) {
        float4 xr[8];
        #pragma unroll
        for (int i = 0; i < 8; i++)
            xr[i] = Xs4[(ty * 8 + i) * (XPAD / 4) + k4];
        float4 wr[4];
        #pragma unroll
        for (int kk = 0; kk < 4; kk++)
            wr[kk] = WsT4[(k4 * 4 + kk) * (XPAD / 4) + tx];
        #pragma unroll
        for (int kk = 0; kk < 4; kk++) {
            #pragma unroll
            for (int i = 0; i < 8; i++) {
                float xv = (kk == 0) ? xr[i].x : (kk == 1) ? xr[i].y
                         : (kk == 2) ? xr[i].z : xr[i].w;
                acc[i][0] = fmaf(xv, wr[kk].x, acc[i][0]);
                acc[i][1] = fmaf(xv, wr[kk].y, acc[i][1]);
                acc[i][2] = fmaf(xv, wr[kk].z, acc[i][2]);
                acc[i][3] = fmaf(xv, wr[kk].w, acc[i][3]);
            }
        }
    }

    float b0 = __ldg(&b[tx * 4 + 0]);
    float b1 = __ldg(&b[tx * 4 + 1]);
    float b2 = __ldg(&b[tx * 4 + 2]);
    float b3 = __ldg(&b[tx * 4 + 3]);

    float4* h4 = reinterpret_cast<float4*>(g_h);
    #pragma unroll
    for (int i = 0; i < 8; i++) {
        int row = rowbase + ty * 8 + i;
        if (row < NN)
            h4[(size_t)row * 16 + tx] =
                make_float4(acc[i][0] + b0, acc[i][1] + b1,
                            acc[i][2] + b2, acc[i][3] + b3);
    }
}

// ---------------------------------------------------------------- gather-mean (+expmap)
// warp per node; half-warps process 2 edges/iteration, float4 lanes.
template <bool DO_EXP>
__global__ __launch_bounds__(256)
void k_agg(float* __restrict__ x_out, const float* __restrict__ curv) {
    int tid = threadIdx.x;
    int warp = tid >> 5, lane = tid & 31;
    int node = blockIdx.x * 8 + warp;
    if (node >= NN) return;

    int rs = g_start[node];
    int re = g_start[node + 1];

    int lane16 = lane & 15;
    int half   = lane >> 4;

    float4 acc = make_float4(0.f, 0.f, 0.f, 0.f);
    const float4* h4 = reinterpret_cast<const float4*>(g_h);

    for (int eb = rs; eb < re; eb += 32) {
        int idx = eb + lane;
        int sid = (idx < re) ? g_csr[idx] : 0;
        int n = min(32, re - eb);
        int npair = (n + 1) >> 1;
        for (int k = 0; k < npair; k++) {
            int ei = 2 * k + half;
            int s = __shfl_sync(0xffffffffu, sid, ei);
            if (ei < n) {
                float4 v = __ldg(&h4[(size_t)s * 16 + lane16]);
                acc.x += v.x; acc.y += v.y; acc.z += v.z; acc.w += v.w;
            }
        }
    }

    // combine the two half-warps (same chunk lane16 in lane and lane+16)
    acc.x += __shfl_xor_sync(0xffffffffu, acc.x, 16);
    acc.y += __shfl_xor_sync(0xffffffffu, acc.y, 16);
    acc.z += __shfl_xor_sync(0xffffffffu, acc.z, 16);
    acc.w += __shfl_xor_sync(0xffffffffu, acc.w, 16);

    float inv_deg = (re > rs) ? (1.0f / (float)(re - rs)) : 0.0f;
    float4 u = make_float4(acc.x * inv_deg, acc.y * inv_deg,
                           acc.z * inv_deg, acc.w * inv_deg);

    float factor = 1.0f;
    if (DO_EXP) {
        float ss = u.x * u.x + u.y * u.y + u.z * u.z + u.w * u.w;
        #pragma unroll
        for (int off = 8; off > 0; off >>= 1)
            ss += __shfl_xor_sync(0xffffffffu, ss, off);
        float c = fabsf(__ldg(&curv[0]));
        float sc = sqrtf(c);
        float norm = fmaxf(sqrtf(ss), EPSN);
        factor = tanhf(sc * norm) / (sc * norm);
    }

    if (half == 0) {
        reinterpret_cast<float4*>(x_out)[(size_t)node * 16 + lane16] =
            make_float4(u.x * factor, u.y * factor, u.z * factor, u.w * factor);
    }
}

// ---------------------------------------------------------------- launch
extern "C" void kernel_launch(void* const* d_in, const int* in_sizes, int n_in,
                              void* d_out, int out_size) {
    const int*   src  = (const int*)d_in[0];
    const int*   dst  = (const int*)d_in[1];
    const float* emb  = (const float*)d_in[2];
    const float* W1   = (const float*)d_in[3];
    const float* b1   = (const float*)d_in[4];
    const float* W2   = (const float*)d_in[5];
    const float* b2   = (const float*)d_in[6];
    const float* curv = (const float*)d_in[7];
    const int E = in_sizes[0];
    float* out = (float*)d_out;

    const int smem_bytes = (128 * XPAD + 64 * XPAD) * sizeof(float);
    cudaFuncSetAttribute(k_linear<true>,  cudaFuncAttributeMaxDynamicSharedMemorySize, smem_bytes);
    cudaFuncSetAttribute(k_linear<false>, cudaFuncAttributeMaxDynamicSharedMemorySize, smem_bytes);

    const int lin_blocks  = (NN + 127) / 128;
    const int node_blocks = (NN + 7) / 8;

    // CSR build (reused by both layers)
    k_zero_deg<<<(NN + 255) / 256, 256>>>();
    k_deg<<<(E + 255) / 256, 256>>>(dst, E);
    k_scan_local<<<NB, SCANB>>>();
    k_scan_add<<<NB, SCANB>>>();
    k_fill<<<(E + 255) / 256, 256>>>(src, dst, E);

    // layer 1: emb -> h1 -> m1 (tangent mean; expmap/logmap roundtrip cancels)
    k_linear<true><<<lin_blocks, 256, smem_bytes>>>(emb, W1, b1, curv);
    k_agg<false><<<node_blocks, 256>>>(g_x, curv);

    // layer 2: m1 -> h2 -> out (with expmap)
    k_linear<false><<<lin_blocks, 256, smem_bytes>>>(g_x, W2, b2, curv);
    k_agg<true><<<node_blocks, 256>>>(out, curv);
}